// round 16
// baseline (speedup 1.0000x reference)
#include <cuda_runtime.h>
#include <math.h>

// ---------------------------------------------------------------------------
// Problem constants (fixed by the dataset)
// ---------------------------------------------------------------------------
#define NATOMS  60000
#define MNBR    12
#define OA      92
#define NB      41
#define FDIM    64
#define KDIM    169      // 2F + NB
#define CDIM    128      // 2F
#define OE      8
#define EDIM    16
#define HDIM    128
#define BCRYS   2048
#define NCONV   3
#define APB     4        // atoms per conv block

// ---------------------------------------------------------------------------
// Scratch (device globals -- no allocation allowed)
// ---------------------------------------------------------------------------
__device__ float g_x0[NATOMS * FDIM];
__device__ float g_x1[NATOMS * FDIM];
__device__ float g_extra[BCRYS * EDIM];
__device__ float g_pool[BCRYS * FDIM];
__device__ float g_cnt[BCRYS];

// ---------------------------------------------------------------------------
// Math helpers
// ---------------------------------------------------------------------------
__device__ __forceinline__ float softplusf(float x) {
    return fmaxf(x, 0.0f) + log1pf(expf(-fabsf(x)));
}
__device__ __forceinline__ float sigmoidf(float x) {
    return 1.0f / (1.0f + expf(-x));
}

// fma.rn.f32x2: acc.{lo,hi} += a{0,1} * b.{lo,hi}   (Blackwell packed fp32)
__device__ __forceinline__ void fma2(unsigned long long &acc, float a0, float a1,
                                     unsigned long long b) {
    unsigned long long av;
    asm("mov.b64 %0, {%1,%2};" : "=l"(av) : "f"(a0), "f"(a1));
    asm("fma.rn.f32x2 %0, %1, %2, %0;" : "+l"(acc) : "l"(av), "l"(b));
}

// ---------------------------------------------------------------------------
// Kernel 1: atom embedding  x = atom_fea @ W_embed + b_embed   [N,92]@[92,64]
// 4 atoms per block, 256 threads (atom = tid/64, col = tid%64)
// ---------------------------------------------------------------------------
__global__ __launch_bounds__(256) void embed_kernel(
    const float* __restrict__ af, const float* __restrict__ W,
    const float* __restrict__ b, float* __restrict__ xo)
{
    __shared__ float s_af[4 * OA];
    const int tid = threadIdx.x;
    const int atom0 = blockIdx.x * 4;
    for (int v = tid; v < 4 * OA; v += 256)
        s_af[v] = af[atom0 * OA + v];   // 4 consecutive rows, contiguous
    __syncthreads();
    const int a = tid >> 6, col = tid & 63;
    float acc = b[col];
    #pragma unroll 4
    for (int k = 0; k < OA; k++)
        acc += s_af[a * OA + k] * W[k * FDIM + col];
    xo[(atom0 + a) * FDIM + col] = acc;
}

// ---------------------------------------------------------------------------
// Kernel 2: extra embedding  softplus(bn(extra_fea @ W_extra + b_extra))
// ---------------------------------------------------------------------------
__global__ void extra_kernel(const float* __restrict__ ef,
                             const float* __restrict__ W,
                             const float* __restrict__ b,
                             const float* __restrict__ g,
                             const float* __restrict__ bb)
{
    const int idx = blockIdx.x * blockDim.x + threadIdx.x;
    if (idx >= BCRYS * EDIM) return;
    const int bc = idx >> 4, e = idx & 15;
    float acc = b[e];
    #pragma unroll
    for (int o = 0; o < OE; o++)
        acc += ef[bc * OE + o] * W[o * EDIM + e];
    const float rs = rsqrtf(1.0f + 1e-5f);
    g_extra[idx] = softplusf(acc * (g[e] * rs) + bb[e]);
}

// ---------------------------------------------------------------------------
// Kernel 3: one CGCNN conv layer, fully fused.
// Block = 128 threads, 4 atoms. Thread owns one output column (of 128) for
// all 4 atoms x 12 neighbors. Gathered inputs in smem interleaved
// [m][k][a0..a3] so one broadcast LDS.128 feeds two fma.rn.f32x2.
// ---------------------------------------------------------------------------
__global__ __launch_bounds__(128) void conv_kernel(
    const float* __restrict__ x, float* __restrict__ xo,
    const float* __restrict__ nbr_fea, const int* __restrict__ nbr_idx,
    const float* __restrict__ W, const float* __restrict__ bias,
    const float* __restrict__ g1, const float* __restrict__ b1,
    const float* __restrict__ g2, const float* __restrict__ b2)
{
    __shared__ __align__(16) float s_in[MNBR * KDIM * APB];   // 32448 B
    __shared__ int s_idx[APB * MNBR];

    const int tid = threadIdx.x;
    const int atom0 = blockIdx.x * APB;   // 60000 % 4 == 0

    if (tid < APB * MNBR) {
        const int a = tid / MNBR, m = tid % MNBR;
        s_idx[tid] = nbr_idx[(atom0 + a) * MNBR + m];
    }
    __syncthreads();

    // ---- gather: build [m][k][a] interleaved tile ----
    for (int v = tid; v < MNBR * KDIM * APB; v += 128) {
        const int a = v & 3;
        const int r = v >> 2;
        const int k = r % KDIM;
        const int m = r / KDIM;
        const int i = atom0 + a;
        float val;
        if (k < FDIM)            val = x[i * FDIM + k];
        else if (k < 2 * FDIM)   val = x[s_idx[a * MNBR + m] * FDIM + (k - FDIM)];
        else                     val = nbr_fea[(i * MNBR + m) * NB + (k - 2 * FDIM)];
        s_in[v] = val;
    }
    __syncthreads();

    // ---- GEMM: out[a][m][col] = sum_k in[a][m][k] * W[k][col] ----
    const int col = tid;
    unsigned long long acc01[MNBR], acc23[MNBR];
    #pragma unroll
    for (int m = 0; m < MNBR; m++) { acc01[m] = 0ULL; acc23[m] = 0ULL; }

    const float* __restrict__ Wc = W + col;
    const float4* __restrict__ sv = reinterpret_cast<const float4*>(s_in);
    for (int k = 0; k < KDIM; k++) {
        const float w = Wc[k * CDIM];
        unsigned long long wd;
        asm("mov.b64 %0, {%1,%1};" : "=l"(wd) : "f"(w));
        #pragma unroll
        for (int m = 0; m < MNBR; m++) {
            const float4 vv = sv[m * KDIM + k];   // broadcast LDS.128
            fma2(acc01[m], vv.x, vv.y, wd);
            fma2(acc23[m], vv.z, vv.w, wd);
        }
    }

    // ---- epilogue: bias + BN1 + gate activations into smem ----
    const float rs = rsqrtf(1.0f + 1e-5f);
    const float s1 = g1[col] * rs;
    const float o1 = bias[col] * s1 + b1[col];
    const bool isFlt = (col < FDIM);

    __syncthreads();                 // done reading s_in; reuse as s_act
    float* s_act = s_in;             // [a][m][col] : 4*12*128 = 6144 floats

    #pragma unroll
    for (int m = 0; m < MNBR; m++) {
        float z0, z1, z2, z3;
        asm("mov.b64 {%0,%1}, %2;" : "=f"(z0), "=f"(z1) : "l"(acc01[m]));
        asm("mov.b64 {%0,%1}, %2;" : "=f"(z2), "=f"(z3) : "l"(acc23[m]));
        float zz[4] = {z0, z1, z2, z3};
        #pragma unroll
        for (int a = 0; a < APB; a++) {
            const float z = zz[a] * s1 + o1;
            s_act[(a * MNBR + m) * CDIM + col] = isFlt ? sigmoidf(z) : softplusf(z);
        }
    }
    __syncthreads();

    // ---- reduce over M, BN2, residual softplus ----
    for (int p = tid; p < APB * FDIM; p += 128) {
        const int a = p >> 6;
        const int j = p & 63;
        float s = 0.0f;
        #pragma unroll
        for (int m = 0; m < MNBR; m++) {
            const float fl = s_act[(a * MNBR + m) * CDIM + j];
            const float co = s_act[(a * MNBR + m) * CDIM + FDIM + j];
            s += fl * co;
        }
        const float z = s * (g2[j] * rs) + b2[j];
        const int i = atom0 + a;
        xo[i * FDIM + j] = softplusf(x[i * FDIM + j] + z);
    }
}

// ---------------------------------------------------------------------------
// Kernel 4: zero the pooling buffers
// ---------------------------------------------------------------------------
__global__ void zero_kernel()
{
    const int idx = blockIdx.x * blockDim.x + threadIdx.x;
    if (idx < BCRYS * FDIM) g_pool[idx] = 0.0f;
    if (idx < BCRYS)        g_cnt[idx]  = 0.0f;
}

// ---------------------------------------------------------------------------
// Kernel 5: segment-sum pooling via float atomics
// ---------------------------------------------------------------------------
__global__ void pool_kernel(const float* __restrict__ x,
                            const int* __restrict__ seg)
{
    const int idx = blockIdx.x * blockDim.x + threadIdx.x;
    if (idx >= NATOMS * FDIM) return;
    const int i = idx >> 6, j = idx & 63;
    const int s = seg[i];
    atomicAdd(&g_pool[s * FDIM + j], x[idx]);
    if (j == 0) atomicAdd(&g_cnt[s], 1.0f);
}

// ---------------------------------------------------------------------------
// Kernel 6: mean + concat + FC + heads (one block per crystal)
// ---------------------------------------------------------------------------
__global__ __launch_bounds__(128) void head_kernel(
    const float* __restrict__ Wfc, const float* __restrict__ bfc,
    const float* __restrict__ W0, const float* __restrict__ b0,
    const float* __restrict__ W1, const float* __restrict__ b1,
    const float* __restrict__ W2, const float* __restrict__ b2,
    float* __restrict__ out)
{
    __shared__ float s_c[FDIM + EDIM];
    __shared__ float s_h[HDIM];
    __shared__ float s_r[4];
    const int b = blockIdx.x, tid = threadIdx.x;

    if (tid < FDIM)
        s_c[tid] = g_pool[b * FDIM + tid] / fmaxf(g_cnt[b], 1.0f);
    else if (tid < FDIM + EDIM)
        s_c[tid] = g_extra[b * EDIM + (tid - FDIM)];
    __syncthreads();

    float acc = bfc[tid];
    #pragma unroll 4
    for (int k = 0; k < FDIM + EDIM; k++)
        acc += s_c[k] * Wfc[k * HDIM + tid];
    s_h[tid] = softplusf(acc);
    __syncthreads();

    const int w = tid >> 5, lane = tid & 31;
    float p = 0.0f;
    #pragma unroll
    for (int t = lane; t < HDIM; t += 32) {
        const float h = s_h[t];
        const float wv = (w == 0) ? W0[t]
                       : (w == 1) ? W1[2 * t]
                       : (w == 2) ? W1[2 * t + 1]
                       :            W2[t];
        p += h * wv;
    }
    #pragma unroll
    for (int off = 16; off; off >>= 1)
        p += __shfl_down_sync(0xffffffff, p, off);
    if (lane == 0) s_r[w] = p;
    __syncthreads();

    if (tid == 0) {
        const float y0  = s_r[0] + b0[0];
        const float y1a = s_r[1] + b1[0];
        const float y1b = s_r[2] + b1[1];
        const float y2  = s_r[3] + b2[0];
        out[b] = y0;                                  // out0 [B,1]
        const float mx = fmaxf(y1a, y1b);
        const float ls = mx + logf(expf(y1a - mx) + expf(y1b - mx));
        out[BCRYS + 2 * b]     = y1a - ls;            // out1 [B,2] (log_softmax)
        out[BCRYS + 2 * b + 1] = y1b - ls;
        out[3 * BCRYS + b]     = y2;                  // out2 [B,1]
    }
}

// ---------------------------------------------------------------------------
// Launch
// ---------------------------------------------------------------------------
extern "C" void kernel_launch(void* const* d_in, const int* in_sizes, int n_in,
                              void* d_out, int out_size)
{
    const float* atom_fea  = (const float*)d_in[0];
    const float* nbr_fea   = (const float*)d_in[1];
    const int*   nbr_idx   = (const int*)  d_in[2];
    const int*   seg       = (const int*)  d_in[3];
    const float* extra_fea = (const float*)d_in[4];
    const float* W_embed   = (const float*)d_in[5];
    const float* b_embed   = (const float*)d_in[6];
    const float* conv_W    = (const float*)d_in[7];
    const float* conv_b    = (const float*)d_in[8];
    const float* bn1_g     = (const float*)d_in[9];
    const float* bn1_b     = (const float*)d_in[10];
    const float* bn2_g     = (const float*)d_in[11];
    const float* bn2_b     = (const float*)d_in[12];
    const float* W_extra   = (const float*)d_in[13];
    const float* b_extra   = (const float*)d_in[14];
    const float* bnx_g     = (const float*)d_in[15];
    const float* bnx_b     = (const float*)d_in[16];
    const float* W_fc      = (const float*)d_in[17];
    const float* b_fc      = (const float*)d_in[18];
    const float* W_out0    = (const float*)d_in[19];
    const float* b_out0    = (const float*)d_in[20];
    const float* W_out1    = (const float*)d_in[21];
    const float* b_out1    = (const float*)d_in[22];
    const float* W_out2    = (const float*)d_in[23];
    const float* b_out2    = (const float*)d_in[24];
    float* out = (float*)d_out;

    float *x0, *x1;
    cudaGetSymbolAddress((void**)&x0, g_x0);
    cudaGetSymbolAddress((void**)&x1, g_x1);

    embed_kernel<<<NATOMS / 4, 256>>>(atom_fea, W_embed, b_embed, x0);
    extra_kernel<<<(BCRYS * EDIM + 255) / 256, 256>>>(extra_fea, W_extra, b_extra,
                                                      bnx_g, bnx_b);
    zero_kernel<<<(BCRYS * FDIM + 255) / 256, 256>>>();

    const float* xin = x0;
    float* xout = x1;
    for (int l = 0; l < NCONV; l++) {
        conv_kernel<<<NATOMS / APB, 128>>>(
            xin, xout, nbr_fea, nbr_idx,
            conv_W + l * KDIM * CDIM, conv_b + l * CDIM,
            bn1_g + l * CDIM, bn1_b + l * CDIM,
            bn2_g + l * FDIM, bn2_b + l * FDIM);
        float* t = xout; xout = (float*)xin; xin = t;
    }
    // after 3 layers (odd count), result is in x1 == xin

    pool_kernel<<<(NATOMS * FDIM + 255) / 256, 256>>>(xin, seg);
    head_kernel<<<BCRYS, 128>>>(W_fc, b_fc, W_out0, b_out0,
                                W_out1, b_out1, W_out2, b_out2, out);
}

// round 17
// speedup vs baseline: 1.1257x; 1.1257x over previous
#include <cuda_runtime.h>
#include <math.h>

// ---------------------------------------------------------------------------
// Problem constants (fixed by the dataset)
// ---------------------------------------------------------------------------
#define NATOMS  60000
#define MNBR    12
#define OA      92
#define NB      41
#define FDIM    64
#define KDIM    169      // 2F + NB
#define CDIM    128      // 2F
#define KNBR    105      // F + NB (per-neighbor part of K)
#define OE      8
#define EDIM    16
#define HDIM    128
#define BCRYS   2048
#define NCONV   3
#define APB     4        // atoms per conv block

// ---------------------------------------------------------------------------
// Scratch (device globals -- no allocation allowed)
// ---------------------------------------------------------------------------
__device__ float g_x0[NATOMS * FDIM];
__device__ float g_x1[NATOMS * FDIM];
__device__ float g_extra[BCRYS * EDIM];
__device__ float g_pool[BCRYS * FDIM];
__device__ float g_cnt[BCRYS];

// ---------------------------------------------------------------------------
// Math helpers
// ---------------------------------------------------------------------------
__device__ __forceinline__ float softplusf(float x) {
    return fmaxf(x, 0.0f) + log1pf(expf(-fabsf(x)));
}
__device__ __forceinline__ float sigmoidf(float x) {
    return 1.0f / (1.0f + expf(-x));
}

// fma.rn.f32x2 with a pre-packed 64-bit multiplicand (no per-FMA MOV pack)
__device__ __forceinline__ void fma2d(unsigned long long &acc,
                                      unsigned long long av,
                                      unsigned long long b) {
    asm("fma.rn.f32x2 %0, %1, %2, %0;" : "+l"(acc) : "l"(av), "l"(b));
}
__device__ __forceinline__ unsigned long long dup2(float w) {
    unsigned long long wd;
    asm("mov.b64 %0, {%1,%1};" : "=l"(wd) : "f"(w));
    return wd;
}
__device__ __forceinline__ void unpack2(unsigned long long v, float &lo, float &hi) {
    asm("mov.b64 {%0,%1}, %2;" : "=f"(lo), "=f"(hi) : "l"(v));
}

// ---------------------------------------------------------------------------
// Kernel 1: atom embedding  x = atom_fea @ W_embed + b_embed   [N,92]@[92,64]
// ---------------------------------------------------------------------------
__global__ __launch_bounds__(256) void embed_kernel(
    const float* __restrict__ af, const float* __restrict__ W,
    const float* __restrict__ b, float* __restrict__ xo)
{
    __shared__ float s_af[4 * OA];
    const int tid = threadIdx.x;
    const int atom0 = blockIdx.x * 4;
    for (int v = tid; v < 4 * OA; v += 256)
        s_af[v] = af[atom0 * OA + v];
    __syncthreads();
    const int a = tid >> 6, col = tid & 63;
    float acc = b[col];
    #pragma unroll 4
    for (int k = 0; k < OA; k++)
        acc += s_af[a * OA + k] * W[k * FDIM + col];
    xo[(atom0 + a) * FDIM + col] = acc;
}

// ---------------------------------------------------------------------------
// Kernel 2: extra embedding  softplus(bn(extra_fea @ W_extra + b_extra))
// ---------------------------------------------------------------------------
__global__ void extra_kernel(const float* __restrict__ ef,
                             const float* __restrict__ W,
                             const float* __restrict__ b,
                             const float* __restrict__ g,
                             const float* __restrict__ bb)
{
    const int idx = blockIdx.x * blockDim.x + threadIdx.x;
    if (idx >= BCRYS * EDIM) return;
    const int bc = idx >> 4, e = idx & 15;
    float acc = b[e];
    #pragma unroll
    for (int o = 0; o < OE; o++)
        acc += ef[bc * OE + o] * W[o * EDIM + e];
    const float rs = rsqrtf(1.0f + 1e-5f);
    g_extra[idx] = softplusf(acc * (g[e] * rs) + bb[e]);
}

// ---------------------------------------------------------------------------
// Kernel 3: one CGCNN conv layer, fully fused.
// Block = 128 threads, 4 atoms. Thread owns one output column (of 128).
// Self part of the GEMM (k<64, identical across all 12 neighbors) is computed
// ONCE and used to initialize all 12 accumulators; the per-neighbor loop runs
// only over the remaining 105 k's. smem tiles are interleaved [..][k][a0..a3]
// so one LDS.128 yields two pre-packed f32x2 operands (zero pack MOVs).
// ---------------------------------------------------------------------------
__global__ __launch_bounds__(128, 6) void conv_kernel(
    const float* __restrict__ x, float* __restrict__ xo,
    const float* __restrict__ nbr_fea, const int* __restrict__ nbr_idx,
    const float* __restrict__ W, const float* __restrict__ bias,
    const float* __restrict__ g1, const float* __restrict__ b1,
    const float* __restrict__ g2, const float* __restrict__ b2)
{
    __shared__ __align__(16) float s_self[FDIM * APB];         // 1 KB
    __shared__ __align__(16) float s_nbr[MNBR * KNBR * APB];   // 20160 B
    __shared__ int s_idx[MNBR * APB];

    const int tid  = threadIdx.x;
    const int lane = tid & 31;
    const int wid  = tid >> 5;
    const int atom0 = blockIdx.x * APB;   // 60000 % 4 == 0

    if (tid < MNBR * APB) {
        const int a = tid & 3, m = tid >> 2;
        s_idx[tid] = nbr_idx[(atom0 + a) * MNBR + m];   // s_idx[m*4+a]
    }
    // self tile: s_self[k*4 + a]
    for (int v = tid; v < FDIM * APB; v += 128) {
        const int a = v & 3, k = v >> 2;
        s_self[v] = x[(atom0 + a) * FDIM + k];
    }
    __syncthreads();

    // neighbor tiles: per-(m,a) coalesced row copy -> s_nbr[(m*105+kk)*4 + a]
    for (int p = wid; p < MNBR * APB; p += 4) {
        const int a = p & 3, m = p >> 2;
        const int nb = s_idx[(m << 2) | a];
        const float* __restrict__ src1 = x + nb * FDIM;
        const float* __restrict__ src2 = nbr_fea + ((atom0 + a) * MNBR + m) * NB;
        for (int kk = lane; kk < KNBR; kk += 32) {
            const float val = (kk < FDIM) ? src1[kk] : src2[kk - FDIM];
            s_nbr[(m * KNBR + kk) * APB + a] = val;
        }
    }
    __syncthreads();

    // ---- GEMM ----
    const int col = tid;
    const float* __restrict__ Wc = W + col;

    // self part: S[a][col] = sum_{k<64} self[a][k] * W[k][col]
    unsigned long long aS01 = 0ULL, aS23 = 0ULL;
    const ulonglong2* __restrict__ sS = reinterpret_cast<const ulonglong2*>(s_self);
    #pragma unroll 4
    for (int k = 0; k < FDIM; k++) {
        const unsigned long long wd = dup2(Wc[k * CDIM]);
        const ulonglong2 vv = sS[k];
        fma2d(aS01, vv.x, wd);
        fma2d(aS23, vv.y, wd);
    }

    unsigned long long acc01[MNBR], acc23[MNBR];
    #pragma unroll
    for (int m = 0; m < MNBR; m++) { acc01[m] = aS01; acc23[m] = aS23; }

    // neighbor part: k = 64 .. 168
    const ulonglong2* __restrict__ sN = reinterpret_cast<const ulonglong2*>(s_nbr);
    #pragma unroll 1
    for (int kk = 0; kk < KNBR; kk++) {
        const unsigned long long wd = dup2(Wc[(FDIM + kk) * CDIM]);
        #pragma unroll
        for (int m = 0; m < MNBR; m++) {
            const ulonglong2 vv = sN[m * KNBR + kk];
            fma2d(acc01[m], vv.x, wd);
            fma2d(acc23[m], vv.y, wd);
        }
    }

    // ---- epilogue ----
    const float rs = rsqrtf(1.0f + 1e-5f);
    const float s1 = g1[col] * rs;
    const float o1 = bias[col] * s1 + b1[col];

    __syncthreads();                       // all GEMM smem reads done
    float* s_core = s_nbr;                 // reuse: [m][a][j], 3072 floats

    if (col >= FDIM) {                     // warps 2-3: softplus(core) -> smem
        const int j = col - FDIM;
        #pragma unroll
        for (int m = 0; m < MNBR; m++) {
            float z0, z1, z2, z3;
            unpack2(acc01[m], z0, z1);
            unpack2(acc23[m], z2, z3);
            s_core[(m * APB + 0) * FDIM + j] = softplusf(z0 * s1 + o1);
            s_core[(m * APB + 1) * FDIM + j] = softplusf(z1 * s1 + o1);
            s_core[(m * APB + 2) * FDIM + j] = softplusf(z2 * s1 + o1);
            s_core[(m * APB + 3) * FDIM + j] = softplusf(z3 * s1 + o1);
        }
    }
    __syncthreads();

    if (col < FDIM) {                      // warps 0-1: sigmoid(flt)*core, reduce
        const int j = col;
        float sum0 = 0.0f, sum1 = 0.0f, sum2 = 0.0f, sum3 = 0.0f;
        #pragma unroll
        for (int m = 0; m < MNBR; m++) {
            float z0, z1, z2, z3;
            unpack2(acc01[m], z0, z1);
            unpack2(acc23[m], z2, z3);
            sum0 += sigmoidf(z0 * s1 + o1) * s_core[(m * APB + 0) * FDIM + j];
            sum1 += sigmoidf(z1 * s1 + o1) * s_core[(m * APB + 1) * FDIM + j];
            sum2 += sigmoidf(z2 * s1 + o1) * s_core[(m * APB + 2) * FDIM + j];
            sum3 += sigmoidf(z3 * s1 + o1) * s_core[(m * APB + 3) * FDIM + j];
        }
        const float s2 = g2[j] * rs;
        const float o2 = b2[j];
        float sums[4] = {sum0, sum1, sum2, sum3};
        #pragma unroll
        for (int a = 0; a < APB; a++) {
            const int i = atom0 + a;
            const float z = sums[a] * s2 + o2;
            xo[i * FDIM + j] = softplusf(x[i * FDIM + j] + z);
        }
    }
}

// ---------------------------------------------------------------------------
// Kernel 4: zero the pooling buffers
// ---------------------------------------------------------------------------
__global__ void zero_kernel()
{
    const int idx = blockIdx.x * blockDim.x + threadIdx.x;
    if (idx < BCRYS * FDIM) g_pool[idx] = 0.0f;
    if (idx < BCRYS)        g_cnt[idx]  = 0.0f;
}

// ---------------------------------------------------------------------------
// Kernel 5: segment-sum pooling via float atomics
// ---------------------------------------------------------------------------
__global__ void pool_kernel(const float* __restrict__ x,
                            const int* __restrict__ seg)
{
    const int idx = blockIdx.x * blockDim.x + threadIdx.x;
    if (idx >= NATOMS * FDIM) return;
    const int i = idx >> 6, j = idx & 63;
    const int s = seg[i];
    atomicAdd(&g_pool[s * FDIM + j], x[idx]);
    if (j == 0) atomicAdd(&g_cnt[s], 1.0f);
}

// ---------------------------------------------------------------------------
// Kernel 6: mean + concat + FC + heads (one block per crystal)
// ---------------------------------------------------------------------------
__global__ __launch_bounds__(128) void head_kernel(
    const float* __restrict__ Wfc, const float* __restrict__ bfc,
    const float* __restrict__ W0, const float* __restrict__ b0,
    const float* __restrict__ W1, const float* __restrict__ b1,
    const float* __restrict__ W2, const float* __restrict__ b2,
    float* __restrict__ out)
{
    __shared__ float s_c[FDIM + EDIM];
    __shared__ float s_h[HDIM];
    __shared__ float s_r[4];
    const int b = blockIdx.x, tid = threadIdx.x;

    if (tid < FDIM)
        s_c[tid] = g_pool[b * FDIM + tid] / fmaxf(g_cnt[b], 1.0f);
    else if (tid < FDIM + EDIM)
        s_c[tid] = g_extra[b * EDIM + (tid - FDIM)];
    __syncthreads();

    float acc = bfc[tid];
    #pragma unroll 4
    for (int k = 0; k < FDIM + EDIM; k++)
        acc += s_c[k] * Wfc[k * HDIM + tid];
    s_h[tid] = softplusf(acc);
    __syncthreads();

    const int w = tid >> 5, lane = tid & 31;
    float p = 0.0f;
    #pragma unroll
    for (int t = lane; t < HDIM; t += 32) {
        const float h = s_h[t];
        const float wv = (w == 0) ? W0[t]
                       : (w == 1) ? W1[2 * t]
                       : (w == 2) ? W1[2 * t + 1]
                       :            W2[t];
        p += h * wv;
    }
    #pragma unroll
    for (int off = 16; off; off >>= 1)
        p += __shfl_down_sync(0xffffffff, p, off);
    if (lane == 0) s_r[w] = p;
    __syncthreads();

    if (tid == 0) {
        const float y0  = s_r[0] + b0[0];
        const float y1a = s_r[1] + b1[0];
        const float y1b = s_r[2] + b1[1];
        const float y2  = s_r[3] + b2[0];
        out[b] = y0;                                  // out0 [B,1]
        const float mx = fmaxf(y1a, y1b);
        const float ls = mx + logf(expf(y1a - mx) + expf(y1b - mx));
        out[BCRYS + 2 * b]     = y1a - ls;            // out1 [B,2] (log_softmax)
        out[BCRYS + 2 * b + 1] = y1b - ls;
        out[3 * BCRYS + b]     = y2;                  // out2 [B,1]
    }
}

// ---------------------------------------------------------------------------
// Launch
// ---------------------------------------------------------------------------
extern "C" void kernel_launch(void* const* d_in, const int* in_sizes, int n_in,
                              void* d_out, int out_size)
{
    const float* atom_fea  = (const float*)d_in[0];
    const float* nbr_fea   = (const float*)d_in[1];
    const int*   nbr_idx   = (const int*)  d_in[2];
    const int*   seg       = (const int*)  d_in[3];
    const float* extra_fea = (const float*)d_in[4];
    const float* W_embed   = (const float*)d_in[5];
    const float* b_embed   = (const float*)d_in[6];
    const float* conv_W    = (const float*)d_in[7];
    const float* conv_b    = (const float*)d_in[8];
    const float* bn1_g     = (const float*)d_in[9];
    const float* bn1_b     = (const float*)d_in[10];
    const float* bn2_g     = (const float*)d_in[11];
    const float* bn2_b     = (const float*)d_in[12];
    const float* W_extra   = (const float*)d_in[13];
    const float* b_extra   = (const float*)d_in[14];
    const float* bnx_g     = (const float*)d_in[15];
    const float* bnx_b     = (const float*)d_in[16];
    const float* W_fc      = (const float*)d_in[17];
    const float* b_fc      = (const float*)d_in[18];
    const float* W_out0    = (const float*)d_in[19];
    const float* b_out0    = (const float*)d_in[20];
    const float* W_out1    = (const float*)d_in[21];
    const float* b_out1    = (const float*)d_in[22];
    const float* W_out2    = (const float*)d_in[23];
    const float* b_out2    = (const float*)d_in[24];
    float* out = (float*)d_out;

    float *x0, *x1;
    cudaGetSymbolAddress((void**)&x0, g_x0);
    cudaGetSymbolAddress((void**)&x1, g_x1);

    embed_kernel<<<NATOMS / 4, 256>>>(atom_fea, W_embed, b_embed, x0);
    extra_kernel<<<(BCRYS * EDIM + 255) / 256, 256>>>(extra_fea, W_extra, b_extra,
                                                      bnx_g, bnx_b);
    zero_kernel<<<(BCRYS * FDIM + 255) / 256, 256>>>();

    const float* xin = x0;
    float* xout = x1;
    for (int l = 0; l < NCONV; l++) {
        conv_kernel<<<NATOMS / APB, 128>>>(
            xin, xout, nbr_fea, nbr_idx,
            conv_W + l * KDIM * CDIM, conv_b + l * CDIM,
            bn1_g + l * CDIM, bn1_b + l * CDIM,
            bn2_g + l * FDIM, bn2_b + l * FDIM);
        float* t = xout; xout = (float*)xin; xin = t;
    }
    // after 3 layers (odd count), result is in x1 == xin

    pool_kernel<<<(NATOMS * FDIM + 255) / 256, 256>>>(xin, seg);
    head_kernel<<<BCRYS, 128>>>(W_fc, b_fc, W_out0, b_out0,
                                W_out1, b_out1, W_out2, b_out2, out);
}